// round 17
// baseline (speedup 1.0000x reference)
#include <cuda_runtime.h>
#include <cuda_fp16.h>
#include <cstdint>
#include <math.h>

#define N_ROWS 4096
#define DIMS   128
#define NJ     4
#define TOPK   16
#define EXS    136      // EX row stride in words (136 mod 32 = 8 -> conflict-free)
#define BCAP   80       // per-row candidate buffer capacity
#define BTRIG  48       // select trigger (48 + 32 <= 80)

// smem map (bytes)
#define SM_AHI  0
#define SM_B0   32768
#define SM_B1   65536
#define SM_EX   98304                     // 128 x 136 uint = 69632
#define SM_BUF  (SM_EX + 128 * EXS * 4)   // 128 x 80 uint = 40960
#define SM_TGT  (SM_BUF + 128 * BCAP * 4) // 4096 bytes
#define SM_TOTAL (SM_TGT + 4096)          // 212992 B

// ---------------- device scratch (static, allocation-free) ----------------
__device__ __half g_fhi[N_ROWS * DIMS];
__device__ __half g_nhi[(size_t)NJ * N_ROWS * DIMS];
__device__ float g_topbuf[N_ROWS * NJ * TOPK];
__device__ float g_part[256];

// ---------------- PTX helpers (base-arch portable: no tcgen05) ----------------
__device__ __forceinline__ uint32_t smem_u32(const void* p) {
    uint32_t a;
    asm("{ .reg .u64 t; cvta.to.shared.u64 t, %1; cvt.u32.u64 %0, t; }" : "=r"(a) : "l"(p));
    return a;
}
__device__ __forceinline__ void ldsm4(uint32_t* r, uint32_t a) {
    asm volatile("ldmatrix.sync.aligned.m8n8.x4.shared.b16 {%0,%1,%2,%3}, [%4];"
                 : "=r"(r[0]), "=r"(r[1]), "=r"(r[2]), "=r"(r[3]) : "r"(a));
}
__device__ __forceinline__ void mma16816(float* c, const uint32_t* a,
                                         uint32_t b0, uint32_t b1) {
    asm("mma.sync.aligned.m16n8k16.row.col.f32.f16.f16.f32 "
        "{%0,%1,%2,%3}, {%4,%5,%6,%7}, {%8,%9}, {%0,%1,%2,%3};"
        : "+f"(c[0]), "+f"(c[1]), "+f"(c[2]), "+f"(c[3])
        : "r"(a[0]), "r"(a[1]), "r"(a[2]), "r"(a[3]), "r"(b0), "r"(b1));
}

// Byte offset of (row, col) in a 128x128 fp16 tile stored as 8-row x 128B
// blocked atoms with SW128 XOR swizzle. col must be a multiple of 8.
__device__ __forceinline__ uint32_t toff(int row, int col) {
    return (uint32_t)(((row >> 3) + (col >> 6) * 16) * 1024 + (row & 7) * 128 +
                      ((((col >> 3) & 7) ^ (row & 7)) * 16));
}

// Stage a 128x128 fp16 tile (row-major in gmem) into swizzled smem via cp.async.
__device__ __forceinline__ void stage_async(uint32_t sdst,
                                            const __half* __restrict__ g,
                                            int t) {
#pragma unroll
    for (int i = 0; i < 4; i++) {
        int c = t + 512 * i;              // 0..2047 16B chunks
        int row = c >> 4, kch = c & 15;
        uint32_t dst = sdst + toff(row, kch * 8);
        const void* src = g + row * DIMS + kch * 8;
        asm volatile("cp.async.cg.shared.global [%0], [%1], 16;" :: "r"(dst), "l"(src));
    }
}

// float <-> order-preserving uint
__device__ __forceinline__ uint32_t fsort(float f) {
    uint32_t u = __float_as_uint(f);
    return ((int)u < 0) ? ~u : (u | 0x80000000u);
}
__device__ __forceinline__ float usort_back(uint32_t u) {
    return (u & 0x80000000u) ? __uint_as_float(u & 0x7fffffffu) : __uint_as_float(~u);
}

// ---------------- warp-collective exact top-16 (uint domain, cnt<=96) ----------------
__device__ __forceinline__ uint32_t select16u(uint32_t* bq, int cnt, int lane,
                                              float* outp) {
    uint32_t x0 = (lane < cnt)      ? bq[lane]      : 0u;
    uint32_t x1 = (lane + 32 < cnt) ? bq[lane + 32] : 0u;
    uint32_t x2 = (lane + 64 < cnt) ? bq[lane + 64] : 0u;
    uint32_t wm = 0;
#pragma unroll 1
    for (int k = 0; k < TOPK; k++) {
        uint32_t lm = max(x0, max(x1, x2));
        wm = __reduce_max_sync(0xffffffffu, lm);
        unsigned b = __ballot_sync(0xffffffffu, lm == wm);
        if (lane == __ffs(b) - 1) {
            if      (x0 == wm) x0 = 0u;
            else if (x1 == wm) x1 = 0u;
            else               x2 = 0u;
        }
        if (lane == 0) {
            bq[k] = wm;
            if (outp) outp[k] = usort_back(wm);
        }
    }
    __syncwarp();
    return wm;
}

// ---------------- kernel 0: normalize + fp16 convert ----------------
__global__ void convert_kernel(const float* __restrict__ feat,
                               const float* __restrict__ negs) {
    int gw = (blockIdx.x * blockDim.x + threadIdx.x) >> 5;
    int lane = threadIdx.x & 31;
    if (gw >= N_ROWS + NJ * N_ROWS) return;
    const float* src;
    __half* dh;
    if (gw < N_ROWS) {
        src = feat + (size_t)gw * DIMS;
        dh = g_fhi + (size_t)gw * DIMS;
    } else {
        int r = gw - N_ROWS;
        src = negs + (size_t)r * DIMS;
        dh = g_nhi + (size_t)r * DIMS;
    }
    float4 v = ((const float4*)src)[lane];
    float s = v.x * v.x + v.y * v.y + v.z * v.z + v.w * v.w;
#pragma unroll
    for (int off = 16; off; off >>= 1) s += __shfl_xor_sync(0xffffffffu, s, off);
    float rinv = 1.0f / fmaxf(sqrtf(s), 1e-12f);
    __half2* dh2 = (__half2*)(dh + 4 * lane);
    dh2[0] = __floats2half2_rn(v.x * rinv, v.y * rinv);
    dh2[1] = __floats2half2_rn(v.z * rinv, v.w * rinv);
}

// ---------------- kernel 1: fused HMMA GEMM (fp16) + per-row exact top-16 ----------------
// grid (32 queryTiles, NJ), block 512 (16 warps; 4x4 grid of 32q x 32c tiles).
// CTA owns 128 q-rows x ALL 4096 candidates for one j -> no global sims buffer.
// Warp w owns rows [8w, 8w+8) for the merge/top-k phase.
__global__ void __launch_bounds__(512, 1)
gemm_topk_kernel(const int* __restrict__ target, const int* __restrict__ idxp) {
    extern __shared__ char smem[];
    const int t = threadIdx.x, wid = t >> 5, lane = t & 31;
    const int n0 = blockIdx.x * 128;
    const int j  = blockIdx.y;
    const uint32_t sb = smem_u32(smem);
    const bool maskj = (j == *idxp);
    const unsigned lmask = (1u << lane) - 1u;

    uint32_t* ex   = (uint32_t*)(smem + SM_EX);
    uint32_t* buf  = (uint32_t*)(smem + SM_BUF);
    uint8_t*  tgt8 = (uint8_t*)(smem + SM_TGT);

    const __half* nh = g_nhi + (size_t)j * N_ROWS * DIMS;

    // prologue: A (queries, staged once) + B tile 0
    stage_async(sb + SM_AHI, g_fhi + (size_t)n0 * DIMS, t);
    stage_async(sb + SM_B0, nh, t);
    asm volatile("cp.async.commit_group;");

    // targets as bytes (classes 0..3)
    for (int i = t; i < N_ROWS; i += 512) tgt8[i] = (uint8_t)target[i];
    __syncthreads();

    const int qoff = (wid >> 2) * 32;
    const int coff = (wid & 3) * 32;
    const int a_r  = ((lane >> 3) & 1) * 8 + (lane & 7);
    const int a_c8 = (lane >> 4) * 8;

    // row targets for this thread's C-fragment rows (fixed across iters)
    int rt[2][2];
#pragma unroll
    for (int mi = 0; mi < 2; mi++) {
        rt[mi][0] = tgt8[n0 + qoff + mi * 16 + (lane >> 2)];
        rt[mi][1] = tgt8[n0 + qoff + mi * 16 + (lane >> 2) + 8];
    }

    // per-owned-row running top-16 state (warp-uniform)
    const int rbase = wid * 8;
    uint32_t tau[8];
    int      cnt[8];
#pragma unroll
    for (int r = 0; r < 8; r++) { tau[r] = 0u; cnt[r] = 0; }

#pragma unroll 1
    for (int it = 0; it < 32; ++it) {
        const int cur = it & 1;
        if (it < 31) {
            stage_async(sb + (cur ? SM_B0 : SM_B1), nh + (size_t)(it + 1) * 128 * DIMS, t);
            asm volatile("cp.async.commit_group;");
            asm volatile("cp.async.wait_group 1;");
        } else {
            asm volatile("cp.async.wait_group 0;");
        }
        __syncthreads();   // bar1: B tile ready; also orders prior merge reads of EX

        const uint32_t b_base = sb + (cur ? SM_B1 : SM_B0);

        float c[2][4][4];
#pragma unroll
        for (int mi = 0; mi < 2; mi++)
#pragma unroll
            for (int ni = 0; ni < 4; ni++)
#pragma unroll
                for (int e = 0; e < 4; e++) c[mi][ni][e] = 0.f;

#pragma unroll
        for (int kc = 0; kc < 8; ++kc) {
            uint32_t ah[2][4], bh[2][4];
#pragma unroll
            for (int mi = 0; mi < 2; mi++) {
                uint32_t off = toff(qoff + mi * 16 + a_r, kc * 16 + a_c8);
                ldsm4(ah[mi], sb + SM_AHI + off);
            }
#pragma unroll
            for (int g = 0; g < 2; g++) {
                uint32_t off = toff(coff + g * 16 + a_r, kc * 16 + a_c8);
                ldsm4(bh[g], b_base + off);
            }
#pragma unroll
            for (int mi = 0; mi < 2; mi++)
#pragma unroll
                for (int ni = 0; ni < 4; ni++) {
                    const int g = ni >> 1, sl = ni & 1;
                    mma16816(c[mi][ni], ah[mi], bh[g][sl], bh[g][2 + sl]);
                }
        }

        // ---- epilogue: mask + sortable-uint -> EX[128][EXS] (smem) ----
        const int cand0 = it * 128;
#pragma unroll
        for (int mi = 0; mi < 2; mi++) {
            const int ql = qoff + mi * 16 + (lane >> 2);
#pragma unroll
            for (int ni = 0; ni < 4; ni++) {
                const int col = coff + ni * 8 + (lane & 3) * 2;
                const int tc0 = tgt8[cand0 + col];
                const int tc1 = tgt8[cand0 + col + 1];
                uint2 v0, v1;
                v0.x = fsort((maskj && tc0 == rt[mi][0]) ? -1e9f : c[mi][ni][0]);
                v0.y = fsort((maskj && tc1 == rt[mi][0]) ? -1e9f : c[mi][ni][1]);
                v1.x = fsort((maskj && tc0 == rt[mi][1]) ? -1e9f : c[mi][ni][2]);
                v1.y = fsort((maskj && tc1 == rt[mi][1]) ? -1e9f : c[mi][ni][3]);
                *(uint2*)&ex[ql * EXS + col]       = v0;
                *(uint2*)&ex[(ql + 8) * EXS + col] = v1;
            }
        }
        __syncthreads();   // bar2: EX complete; also protects B tiles from next cp.async

        // ---- merge: warp-owned rows, screen + exact buffered top-16 ----
#pragma unroll
        for (int r = 0; r < 8; r++) {
            uint4 v = *(const uint4*)&ex[(rbase + r) * EXS + lane * 4];
            uint32_t lmax = max(max(v.x, v.y), max(v.z, v.w));
            uint32_t cmax = __reduce_max_sync(0xffffffffu, lmax);
            if (cmax > tau[r]) {
                uint32_t* br = buf + (rbase + r) * BCAP;
                uint32_t vv[4] = {v.x, v.y, v.z, v.w};
#pragma unroll
                for (int e = 0; e < 4; e++) {
                    bool p = vv[e] > tau[r];
                    unsigned m = __ballot_sync(0xffffffffu, p);
                    if (m) {
                        if (p) br[cnt[r] + __popc(m & lmask)] = vv[e];
                        cnt[r] += __popc(m);
                        __syncwarp();
                        if (cnt[r] > BTRIG) {
                            tau[r] = select16u(br, cnt[r], lane, nullptr);
                            cnt[r] = TOPK;
                        }
                    }
                }
            }
        }
    }

    // ---- final exact top-16 per owned row -> g_topbuf (descending floats) ----
#pragma unroll 1
    for (int r = 0; r < 8; r++) {
        float* outp = g_topbuf + ((size_t)(n0 + rbase + r) * NJ + j) * TOPK;
        select16u(buf + (rbase + r) * BCAP, cnt[r], lane, outp);
    }
}

// ---------------- kernel 2: entropy + decay, fine-grained (one (n,k) per thread) ----------------
__global__ void entropy_kernel() {
    __shared__ float red[256];
    const int id = blockIdx.x * 256 + threadIdx.x;   // 0..65535
    const int n = id >> 4, k = id & 15;
    const float* tb = g_topbuf + (size_t)n * (NJ * TOPK);

    float wsum = 0.f, w = 1.f;
#pragma unroll
    for (int i = 0; i < TOPK; i++) { wsum += w; w *= 0.95f; }
    float wk = 1.f;
    for (int i = 0; i < 16; i++) wk = (i < k) ? wk * 0.95f : wk;

    float l0 = tb[0 * TOPK + k] * 100.0f;
    float l1 = tb[1 * TOPK + k] * 100.0f;
    float l2 = tb[2 * TOPK + k] * 100.0f;
    float l3 = tb[3 * TOPK + k] * 100.0f;
    float m = fmaxf(fmaxf(l0, l1), fmaxf(l2, l3));
    float e0 = expf(l0 - m), e1 = expf(l1 - m), e2 = expf(l2 - m), e3 = expf(l3 - m);
    float s  = e0 + e1 + e2 + e3;
    float t1 = e0 * (l0 - m) + e1 * (l1 - m) + e2 * (l2 - m) + e3 * (l3 - m);
    float ent = t1 / s - logf(s);
    float acc = ent * wk / wsum;

    red[threadIdx.x] = acc;
    __syncthreads();
    for (int off = 128; off; off >>= 1) {
        if (threadIdx.x < off) red[threadIdx.x] += red[threadIdx.x + off];
        __syncthreads();
    }
    if (threadIdx.x == 0) g_part[blockIdx.x] = red[0];
}

// ---------------- kernel 3: deterministic final reduction (256 partials) ----------------
__global__ void final_kernel(float* out) {
    __shared__ float red[256];
    red[threadIdx.x] = g_part[threadIdx.x];
    __syncthreads();
    for (int off = 128; off; off >>= 1) {
        if (threadIdx.x < off) red[threadIdx.x] += red[threadIdx.x + off];
        __syncthreads();
    }
    if (threadIdx.x == 0) out[0] = red[0] / (float)N_ROWS + logf((float)NJ);
}

// ---------------- launch ----------------
extern "C" void kernel_launch(void* const* d_in, const int* in_sizes, int n_in,
                              void* d_out, int out_size) {
    const float* feat   = (const float*)d_in[0];
    const int*   target = (const int*)d_in[1];
    const float* negs   = (const float*)d_in[2];
    const int*   idxp   = (const int*)d_in[3];
    float*       out    = (float*)d_out;

    cudaFuncSetAttribute(gemm_topk_kernel,
                         cudaFuncAttributeMaxDynamicSharedMemorySize, SM_TOTAL);

    convert_kernel<<<(N_ROWS + NJ * N_ROWS) / 8, 256>>>(feat, negs);
    gemm_topk_kernel<<<dim3(N_ROWS / 128, NJ), 512, SM_TOTAL>>>(target, idxp);
    entropy_kernel<<<256, 256>>>();
    final_kernel<<<1, 256>>>(out);
}